// round 4
// baseline (speedup 1.0000x reference)
#include <cuda_runtime.h>
#include <math.h>

#define C_    6
#define A_    1024
#define HW_   16384
#define NROWS 65536
#define NPIX  65536

// ---------------- device scratch ----------------
__device__ float g_sums[C_ * A_];
__device__ float g_cnt[C_];
__device__ float g_protoN[C_ * A_];
__device__ float g_Sc[C_];
__device__ float g_L1;
__device__ float g_L2;

// ---------------- f32x2 packed helpers (sm_100+) ----------------
__device__ __forceinline__ unsigned long long pk(float lo, float hi) {
    unsigned long long r;
    asm("mov.b64 %0, {%1, %2};" : "=l"(r) : "f"(lo), "f"(hi));
    return r;
}
__device__ __forceinline__ void upk(unsigned long long v, float& lo, float& hi) {
    asm("mov.b64 {%0, %1}, %2;" : "=f"(lo), "=f"(hi) : "l"(v));
}
__device__ __forceinline__ unsigned long long fma2(unsigned long long a,
                                                   unsigned long long b,
                                                   unsigned long long c) {
    unsigned long long d;
    asm("fma.rn.f32x2 %0, %1, %2, %3;" : "=l"(d) : "l"(a), "l"(b), "l"(c));
    return d;
}

// ---------------- kernel 0: zero accumulators ----------------
__global__ void zero_kernel() {
    int i = blockIdx.x * blockDim.x + threadIdx.x;
    if (i < C_ * A_) g_sums[i] = 0.f;
    if (i < C_) { g_cnt[i] = 0.f; g_Sc[i] = 0.f; }
    if (i == 0) { g_L1 = 0.f; g_L2 = 0.f; }
}

// ---------------- kernel 1: per-class segment sums of srcfeat ----------------
__device__ __forceinline__ void seg_accum(int c, const float4& v,
                                          float4 acc[6], float cnt[6], bool leader) {
    if ((unsigned)c >= 6u) return;
    switch (c) {
#define SEG_CASE(i) \
        case i: acc[i].x += v.x; acc[i].y += v.y; acc[i].z += v.z; acc[i].w += v.w; \
                if (leader) cnt[i] += 1.0f; break;
        SEG_CASE(0) SEG_CASE(1) SEG_CASE(2) SEG_CASE(3) SEG_CASE(4) SEG_CASE(5)
#undef SEG_CASE
    }
}

__global__ void __launch_bounds__(256, 4) seg_kernel(const float* __restrict__ src,
                                                     const int* __restrict__ labels) {
    const int col = threadIdx.x << 2;
    const bool leader = (threadIdx.x == 0);
    float4 acc[6];
#pragma unroll
    for (int c = 0; c < 6; c++) acc[c] = make_float4(0.f, 0.f, 0.f, 0.f);
    float cnt[6] = {0.f, 0.f, 0.f, 0.f, 0.f, 0.f};

    const int stride = gridDim.x;

    // software pipeline: prefetch group of 2 rows while consuming current 2
    int r = blockIdx.x;
    int lA0, lA1;
    float4 vA0, vA1;
    bool okA0 = (r < NROWS), okA1 = (r + stride < NROWS);
    if (okA0) { lA0 = labels[r];          vA0 = __ldcs((const float4*)(src + (size_t)r * A_ + col)); }
    if (okA1) { lA1 = labels[r + stride]; vA1 = __ldcs((const float4*)(src + (size_t)(r + stride) * A_ + col)); }

    for (int rn = r + 2 * stride; rn < NROWS; rn += 2 * stride) {
        int lB0, lB1;
        float4 vB0, vB1;
        bool okB1 = (rn + stride < NROWS);
        lB0 = labels[rn];
        vB0 = __ldcs((const float4*)(src + (size_t)rn * A_ + col));
        if (okB1) {
            lB1 = labels[rn + stride];
            vB1 = __ldcs((const float4*)(src + (size_t)(rn + stride) * A_ + col));
        }
        // consume current group
        seg_accum(lA0, vA0, acc, cnt, leader);
        if (okA1) seg_accum(lA1, vA1, acc, cnt, leader);
        // shift
        lA0 = lB0; vA0 = vB0; okA0 = true;
        lA1 = lB1; vA1 = vB1; okA1 = okB1;
    }
    if (okA0) seg_accum(lA0, vA0, acc, cnt, leader);
    if (okA1) seg_accum(lA1, vA1, acc, cnt, leader);

#pragma unroll
    for (int c = 0; c < 6; c++) {
        atomicAdd(&g_sums[c * A_ + col + 0], acc[c].x);
        atomicAdd(&g_sums[c * A_ + col + 1], acc[c].y);
        atomicAdd(&g_sums[c * A_ + col + 2], acc[c].z);
        atomicAdd(&g_sums[c * A_ + col + 3], acc[c].w);
    }
    if (leader) {
#pragma unroll
        for (int c = 0; c < 6; c++) atomicAdd(&g_cnt[c], cnt[c]);
    }
}

// ---------------- kernel 2: fused proto-normalize + per-class exp-sum stats ----
__global__ void __launch_bounds__(256) protostats_kernel(const float* __restrict__ Proto,
                                                         const float* __restrict__ tarout) {
    __shared__ float red[256];
    const int tid = threadIdx.x;

    if (blockIdx.x < 6) {
        const int c = blockIdx.x;
        float4 v = *reinterpret_cast<const float4*>(Proto + c * A_ + (tid << 2));
        float ss = v.x * v.x + v.y * v.y + v.z * v.z + v.w * v.w;
        red[tid] = ss;
        __syncthreads();
        for (int s = 128; s > 0; s >>= 1) {
            if (tid < s) red[tid] += red[tid + s];
            __syncthreads();
        }
        const float inv = 1.0f / fmaxf(sqrtf(red[0]), 1e-12f);
        float4 o = make_float4(v.x * inv, v.y * inv, v.z * inv, v.w * inv);
        *reinterpret_cast<float4*>(g_protoN + c * A_ + (tid << 2)) = o;
    } else {
        const int sIdx = blockIdx.x - 6;
        const int base = sIdx << 12;
        const int c = (sIdx >> 2) % 6;
        float acc = 0.f;
#pragma unroll
        for (int k = 0; k < 4; k++) {
            float4 t = __ldcs((const float4*)(tarout + base + k * 1024 + (tid << 2)));
            acc += __expf(t.x) + __expf(t.y) + __expf(t.z) + __expf(t.w);
        }
        red[tid] = acc;
        __syncthreads();
        for (int s = 128; s > 0; s >>= 1) {
            if (tid < s) red[tid] += red[tid + s];
            __syncthreads();
        }
        if (tid == 0) atomicAdd(&g_Sc[c], red[0]);
    }
}

// ---------------- kernel 3: contrast + both loss accumulations ----------------
// 1024 blocks x 128 threads. Block = 64 consecutive pixels of one image.
// Thread owns ONE pixel (pix = tid & 63) and a 512-channel HALF (tid >> 6).
// fma2 pairs adjacent CHANNELS. Explicit double-buffered loads.
__global__ void __launch_bounds__(128, 8) contrast_kernel(const float* __restrict__ tarfeat,
                                                          const float* __restrict__ tarout) {
    __shared__ float sProto[C_ * A_];   // 24 KB
    __shared__ float sEx[7][128];       // 3.5 KB partial exchange
    __shared__ float sRed[4];

    const int tid = threadIdx.x;
    const int lane = tid & 31;
    const int wid = tid >> 5;

    for (int i = tid; i < C_ * A_ / 4; i += 128)
        reinterpret_cast<float4*>(sProto)[i] = reinterpret_cast<const float4*>(g_protoN)[i];
    __syncthreads();

    const int T = blockIdx.x;
    const int b = T >> 8;                 // 256 tiles per image
    const int pixBase = (T & 255) << 6;   // 64 pixels per tile
    const int pixLoc = tid & 63;
    const int half = tid >> 6;            // channel half
    const int chBase = half << 9;         // 0 or 512

    const float* p = tarfeat + (size_t)b * ((size_t)A_ * HW_)
                   + (size_t)chBase * HW_ + pixBase + pixLoc;
    const float* pf = sProto + chBase;    // per-half proto slice base (per class offset added)

    unsigned long long d2[6], ss2 = 0ull;
#pragma unroll
    for (int c = 0; c < 6; c++) d2[c] = 0ull;

    float vA[8], vB[8];
    // prologue: load channels 0..7 of this half
#pragma unroll
    for (int j = 0; j < 8; j++) vA[j] = __ldcs(p + (size_t)j * HW_);
    p += (size_t)8 * HW_;

#pragma unroll 1
    for (int a = 0; a < 512; a += 16) {
        // prefetch channels a+8..a+15
#pragma unroll
        for (int j = 0; j < 8; j++) vB[j] = __ldcs(p + (size_t)j * HW_);
        p += (size_t)8 * HW_;
        // consume vA (channels a..a+7)
#pragma unroll
        for (int jp = 0; jp < 4; jp++) {
            unsigned long long vv = pk(vA[2 * jp], vA[2 * jp + 1]);
            ss2 = fma2(vv, vv, ss2);
#pragma unroll
            for (int c = 0; c < 6; c++) {
                float2 pp = *reinterpret_cast<const float2*>(pf + c * A_ + a + 2 * jp);
                d2[c] = fma2(vv, pk(pp.x, pp.y), d2[c]);
            }
        }
        // prefetch channels a+16..a+23 (skip on last iter)
        if (a + 16 < 512) {
#pragma unroll
            for (int j = 0; j < 8; j++) vA[j] = __ldcs(p + (size_t)j * HW_);
            p += (size_t)8 * HW_;
        }
        // consume vB (channels a+8..a+15)
#pragma unroll
        for (int jp = 0; jp < 4; jp++) {
            unsigned long long vv = pk(vB[2 * jp], vB[2 * jp + 1]);
            ss2 = fma2(vv, vv, ss2);
#pragma unroll
            for (int c = 0; c < 6; c++) {
                float2 pp = *reinterpret_cast<const float2*>(pf + c * A_ + a + 8 + 2 * jp);
                d2[c] = fma2(vv, pk(pp.x, pp.y), d2[c]);
            }
        }
    }

    // fold channel pairs and exchange halves via smem
#pragma unroll
    for (int c = 0; c < 6; c++) {
        float lo, hi;
        upk(d2[c], lo, hi);
        sEx[c][tid] = lo + hi;
    }
    {
        float lo, hi;
        upk(ss2, lo, hi);
        sEx[6][tid] = lo + hi;
    }
    __syncthreads();

    float L1p = 0.f, L2p = 0.f;
    if (tid < 64) {
        float d[6], ss;
#pragma unroll
        for (int c = 0; c < 6; c++) d[c] = sEx[c][tid] + sEx[c][tid + 64];
        ss = sEx[6][tid] + sEx[6][tid + 64];

        const float inv = rsqrtf(fmaxf(ss, 1e-24f));
        const int pix = pixBase + tid;
        const float* to = tarout + (size_t)b * ((size_t)C_ * HW_) + pix;

        float e1[6], s1 = 0.f;
#pragma unroll
        for (int c = 0; c < 6; c++) {
            e1[c] = __expf(to[(size_t)c * HW_]);
            s1 += e1[c];
        }
#pragma unroll
        for (int c = 0; c < 6; c++) {
            float con = d[c] * inv;
            L1p = fmaf(e1[c], con, L1p);
            L2p = fmaf(e1[c] * (1.0f / g_Sc[c]), con, L2p);
        }
        L1p /= s1;
    }

#pragma unroll
    for (int o = 16; o > 0; o >>= 1) {
        L1p += __shfl_xor_sync(0xffffffffu, L1p, o);
        L2p += __shfl_xor_sync(0xffffffffu, L2p, o);
    }
    if (lane == 0 && wid < 2) { sRed[wid] = L1p; sRed[2 + wid] = L2p; }
    __syncthreads();
    if (tid == 0) {
        atomicAdd(&g_L1, sRed[0] + sRed[1]);
        atomicAdd(&g_L2, sRed[2] + sRed[3]);
    }
}

// ---------------- kernel 4: finalize mean + loss ----------------
__global__ void meanfin_kernel(float* __restrict__ out, int out_size) {
    int i = blockIdx.x * blockDim.x + threadIdx.x;
    if (i < C_ * A_ && (i + 1) < out_size)
        out[1 + i] = g_sums[i] / fmaxf(g_cnt[i >> 10], 1.0f);
    if (i == 0 && out_size >= 1) {
        float loss1 = 1.0f - g_L1 * (1.0f / (float)NPIX);
        float loss2 = 1.0f - g_L2 * (1.0f / (float)C_);
        out[0] = loss1 + loss2;
    }
}

// ---------------- launch ----------------
extern "C" void kernel_launch(void* const* d_in, const int* in_sizes, int n_in,
                              void* d_out, int out_size) {
    const float* Proto   = (const float*)d_in[0];
    const float* srcfeat = (const float*)d_in[1];
    const float* tarfeat = (const float*)d_in[2];
    const float* tarout  = (const float*)d_in[3];
    const int* labels    = (const int*)d_in[4];
    float* out = (float*)d_out;

    zero_kernel<<<24, 256>>>();
    seg_kernel<<<592, 256>>>(srcfeat, labels);
    protostats_kernel<<<102, 256>>>(Proto, tarout);
    contrast_kernel<<<1024, 128>>>(tarfeat, tarout);
    meanfin_kernel<<<24, 256>>>(out, out_size);
}

// round 5
// speedup vs baseline: 1.0960x; 1.0960x over previous
#include <cuda_runtime.h>
#include <math.h>

#define C_    6
#define A_    1024
#define HW_   16384
#define NROWS 65536
#define NPIX  65536

// ---------------- device scratch ----------------
__device__ float g_sums[C_ * A_];
__device__ int   g_cnti[C_];
__device__ float g_protoN[C_ * A_];
__device__ float g_Sc[C_];
__device__ float g_L1;
__device__ float g_L2;

// ---------------- f32x2 packed helpers (sm_100+) ----------------
__device__ __forceinline__ unsigned long long pk(float lo, float hi) {
    unsigned long long r;
    asm("mov.b64 %0, {%1, %2};" : "=l"(r) : "f"(lo), "f"(hi));
    return r;
}
__device__ __forceinline__ void upk(unsigned long long v, float& lo, float& hi) {
    asm("mov.b64 {%0, %1}, %2;" : "=f"(lo), "=f"(hi) : "l"(v));
}
__device__ __forceinline__ unsigned long long fma2(unsigned long long a,
                                                   unsigned long long b,
                                                   unsigned long long c) {
    unsigned long long d;
    asm("fma.rn.f32x2 %0, %1, %2, %3;" : "=l"(d) : "l"(a), "l"(b), "l"(c));
    return d;
}

// ---------------- kernel 0: zero accumulators ----------------
__global__ void zero_kernel() {
    int i = blockIdx.x * blockDim.x + threadIdx.x;
    if (i < C_ * A_) g_sums[i] = 0.f;
    if (i < C_) { g_cnti[i] = 0; g_Sc[i] = 0.f; }
    if (i == 0) { g_L1 = 0.f; g_L2 = 0.f; }
}

// ---------------- kernel 1: per-class segment sums of srcfeat (no counts) ----
__device__ __forceinline__ void seg_accum(int c, const float4& v, float4 acc[6]) {
    if ((unsigned)c >= 6u) return;
    switch (c) {
#define SEG_CASE(i) \
        case i: acc[i].x += v.x; acc[i].y += v.y; acc[i].z += v.z; acc[i].w += v.w; break;
        SEG_CASE(0) SEG_CASE(1) SEG_CASE(2) SEG_CASE(3) SEG_CASE(4) SEG_CASE(5)
#undef SEG_CASE
    }
}

__global__ void __launch_bounds__(256, 4) seg_kernel(const float* __restrict__ src,
                                                     const int* __restrict__ labels) {
    const int col = threadIdx.x << 2;
    float4 acc[6];
#pragma unroll
    for (int c = 0; c < 6; c++) acc[c] = make_float4(0.f, 0.f, 0.f, 0.f);

    const int stride = gridDim.x;
    int r = blockIdx.x;
    // 4 rows in flight (64 B/thread of MLP)
    for (; r + 3 * stride < NROWS; r += 4 * stride) {
        int l0 = labels[r];
        int l1 = labels[r + stride];
        int l2 = labels[r + 2 * stride];
        int l3 = labels[r + 3 * stride];
        float4 v0 = __ldcs((const float4*)(src + (size_t)r * A_ + col));
        float4 v1 = __ldcs((const float4*)(src + (size_t)(r + stride) * A_ + col));
        float4 v2 = __ldcs((const float4*)(src + (size_t)(r + 2 * stride) * A_ + col));
        float4 v3 = __ldcs((const float4*)(src + (size_t)(r + 3 * stride) * A_ + col));
        seg_accum(l0, v0, acc);
        seg_accum(l1, v1, acc);
        seg_accum(l2, v2, acc);
        seg_accum(l3, v3, acc);
    }
    for (; r < NROWS; r += stride) {
        int l0 = labels[r];
        float4 v0 = __ldcs((const float4*)(src + (size_t)r * A_ + col));
        seg_accum(l0, v0, acc);
    }

#pragma unroll
    for (int c = 0; c < 6; c++) {
        atomicAdd(&g_sums[c * A_ + col + 0], acc[c].x);
        atomicAdd(&g_sums[c * A_ + col + 1], acc[c].y);
        atomicAdd(&g_sums[c * A_ + col + 2], acc[c].z);
        atomicAdd(&g_sums[c * A_ + col + 3], acc[c].w);
    }
}

// ---------------- kernel 2: proto-normalize + exp-sum stats + label counts ----
// blocks 0..5    : normalize prototype row
// blocks 6..101  : per-class exp-sums over 4096-element tarout chunks
// blocks 102..117: label histogram over 4096-label chunks
__global__ void __launch_bounds__(256) protostats_kernel(const float* __restrict__ Proto,
                                                         const float* __restrict__ tarout,
                                                         const int* __restrict__ labels) {
    __shared__ float red[256];
    const int tid = threadIdx.x;

    if (blockIdx.x < 6) {
        const int c = blockIdx.x;
        float4 v = *reinterpret_cast<const float4*>(Proto + c * A_ + (tid << 2));
        float ss = v.x * v.x + v.y * v.y + v.z * v.z + v.w * v.w;
        red[tid] = ss;
        __syncthreads();
        for (int s = 128; s > 0; s >>= 1) {
            if (tid < s) red[tid] += red[tid + s];
            __syncthreads();
        }
        const float inv = 1.0f / fmaxf(sqrtf(red[0]), 1e-12f);
        float4 o = make_float4(v.x * inv, v.y * inv, v.z * inv, v.w * inv);
        *reinterpret_cast<float4*>(g_protoN + c * A_ + (tid << 2)) = o;
    } else if (blockIdx.x < 102) {
        const int sIdx = blockIdx.x - 6;
        const int base = sIdx << 12;
        const int c = (sIdx >> 2) % 6;
        float acc = 0.f;
#pragma unroll
        for (int k = 0; k < 4; k++) {
            float4 t = __ldcs((const float4*)(tarout + base + k * 1024 + (tid << 2)));
            acc += __expf(t.x) + __expf(t.y) + __expf(t.z) + __expf(t.w);
        }
        red[tid] = acc;
        __syncthreads();
        for (int s = 128; s > 0; s >>= 1) {
            if (tid < s) red[tid] += red[tid + s];
            __syncthreads();
        }
        if (tid == 0) atomicAdd(&g_Sc[c], red[0]);
    } else {
        __shared__ int scnt[6];
        if (tid < 6) scnt[tid] = 0;
        __syncthreads();
        const int base = (blockIdx.x - 102) << 12;
        int cnt[6] = {0, 0, 0, 0, 0, 0};
#pragma unroll
        for (int k = 0; k < 16; k++) {
            int l = labels[base + k * 256 + tid];
#pragma unroll
            for (int c = 0; c < 6; c++) cnt[c] += (l == c);
        }
#pragma unroll
        for (int c = 0; c < 6; c++) {
            int w = __reduce_add_sync(0xffffffffu, cnt[c]);
            if ((tid & 31) == 0 && w) atomicAdd(&scnt[c], w);
        }
        __syncthreads();
        if (tid < 6 && scnt[tid]) atomicAdd(&g_cnti[tid], scnt[tid]);
    }
}

// ---------------- kernel 3: contrast + both loss accumulations ----------------
// 512 blocks x 256 threads. Block = 128 consecutive pixels of one image.
// Thread owns ONE pixel (tid & 127) and a 512-channel half (tid >> 7).
// 16 scalar loads in flight per thread (64 B MLP).
__global__ void __launch_bounds__(256, 4) contrast_kernel(const float* __restrict__ tarfeat,
                                                          const float* __restrict__ tarout) {
    __shared__ float sProto[C_ * A_];   // 24 KB
    __shared__ float sEx[7][256];       // 7 KB
    __shared__ float sRed[16];

    const int tid = threadIdx.x;
    const int lane = tid & 31;
    const int wid = tid >> 5;

    for (int i = tid; i < C_ * A_ / 4; i += 256)
        reinterpret_cast<float4*>(sProto)[i] = reinterpret_cast<const float4*>(g_protoN)[i];
    __syncthreads();

    const int T = blockIdx.x;
    const int b = T >> 7;                 // 128 tiles per image
    const int pixBase = (T & 127) << 7;   // 128 pixels per tile
    const int pixLoc = tid & 127;
    const int chBase = (tid >> 7) << 9;   // 0 or 512

    const float* p = tarfeat + (size_t)b * ((size_t)A_ * HW_)
                   + (size_t)chBase * HW_ + pixBase + pixLoc;
    const float* pf = sProto + chBase;

    unsigned long long d2[6], ss2 = 0ull;
#pragma unroll
    for (int c = 0; c < 6; c++) d2[c] = 0ull;

#pragma unroll 1
    for (int a = 0; a < 512; a += 16) {
        float v[16];
#pragma unroll
        for (int j = 0; j < 16; j++) v[j] = __ldcs(p + (size_t)j * HW_);
        p += (size_t)16 * HW_;
#pragma unroll
        for (int jp = 0; jp < 8; jp++) {
            unsigned long long vv = pk(v[2 * jp], v[2 * jp + 1]);
            ss2 = fma2(vv, vv, ss2);
#pragma unroll
            for (int c = 0; c < 6; c++) {
                float2 pp = *reinterpret_cast<const float2*>(pf + c * A_ + a + 2 * jp);
                d2[c] = fma2(vv, pk(pp.x, pp.y), d2[c]);
            }
        }
    }

    // fold channel pairs; exchange halves via smem
#pragma unroll
    for (int c = 0; c < 6; c++) {
        float lo, hi;
        upk(d2[c], lo, hi);
        sEx[c][tid] = lo + hi;
    }
    {
        float lo, hi;
        upk(ss2, lo, hi);
        sEx[6][tid] = lo + hi;
    }
    __syncthreads();

    float L1p = 0.f, L2p = 0.f;
    if (tid < 128) {
        float d[6], ss;
#pragma unroll
        for (int c = 0; c < 6; c++) d[c] = sEx[c][tid] + sEx[c][tid + 128];
        ss = sEx[6][tid] + sEx[6][tid + 128];

        const float inv = rsqrtf(fmaxf(ss, 1e-24f));
        const int pix = pixBase + tid;
        const float* to = tarout + (size_t)b * ((size_t)C_ * HW_) + pix;

        float e1[6], s1 = 0.f;
#pragma unroll
        for (int c = 0; c < 6; c++) {
            e1[c] = __expf(to[(size_t)c * HW_]);
            s1 += e1[c];
        }
#pragma unroll
        for (int c = 0; c < 6; c++) {
            float con = d[c] * inv;
            L1p = fmaf(e1[c], con, L1p);
            L2p = fmaf(e1[c] * (1.0f / g_Sc[c]), con, L2p);
        }
        L1p /= s1;
    }

#pragma unroll
    for (int o = 16; o > 0; o >>= 1) {
        L1p += __shfl_xor_sync(0xffffffffu, L1p, o);
        L2p += __shfl_xor_sync(0xffffffffu, L2p, o);
    }
    if (lane == 0) { sRed[wid] = L1p; sRed[8 + wid] = L2p; }
    __syncthreads();
    if (tid == 0) {
        float a1 = 0.f, a2 = 0.f;
#pragma unroll
        for (int w = 0; w < 8; w++) { a1 += sRed[w]; a2 += sRed[8 + w]; }
        atomicAdd(&g_L1, a1);
        atomicAdd(&g_L2, a2);
    }
}

// ---------------- kernel 4: finalize mean + loss ----------------
__global__ void meanfin_kernel(float* __restrict__ out, int out_size) {
    int i = blockIdx.x * blockDim.x + threadIdx.x;
    if (i < C_ * A_ && (i + 1) < out_size)
        out[1 + i] = g_sums[i] / fmaxf((float)g_cnti[i >> 10], 1.0f);
    if (i == 0 && out_size >= 1) {
        float loss1 = 1.0f - g_L1 * (1.0f / (float)NPIX);
        float loss2 = 1.0f - g_L2 * (1.0f / (float)C_);
        out[0] = loss1 + loss2;
    }
}

// ---------------- launch ----------------
extern "C" void kernel_launch(void* const* d_in, const int* in_sizes, int n_in,
                              void* d_out, int out_size) {
    const float* Proto   = (const float*)d_in[0];
    const float* srcfeat = (const float*)d_in[1];
    const float* tarfeat = (const float*)d_in[2];
    const float* tarout  = (const float*)d_in[3];
    const int* labels    = (const int*)d_in[4];
    float* out = (float*)d_out;

    zero_kernel<<<24, 256>>>();
    seg_kernel<<<592, 256>>>(srcfeat, labels);
    protostats_kernel<<<118, 256>>>(Proto, tarout, labels);
    contrast_kernel<<<512, 256>>>(tarfeat, tarout);
    meanfin_kernel<<<24, 256>>>(out, out_size);
}

// round 6
// speedup vs baseline: 1.2591x; 1.1488x over previous
#include <cuda_runtime.h>
#include <math.h>

#define C_    6
#define A_    1024
#define HW_   16384
#define NROWS 65536
#define NPIX  65536

#define SEG_GRID   592     // 4 CTAs/SM * 148 SMs
#define CON_TILES  512     // 128-pixel tiles
#define MEGA_GRID  (SEG_GRID + CON_TILES)

// ---------------- device scratch ----------------
__device__ float g_sums[C_ * A_];
__device__ int   g_cnti[C_];
__device__ float g_protoN[C_ * A_];
__device__ float g_Sc[C_];
__device__ float g_L1;
__device__ float g_L2;

// ---------------- f32x2 packed helpers (sm_100+) ----------------
__device__ __forceinline__ unsigned long long pk(float lo, float hi) {
    unsigned long long r;
    asm("mov.b64 %0, {%1, %2};" : "=l"(r) : "f"(lo), "f"(hi));
    return r;
}
__device__ __forceinline__ void upk(unsigned long long v, float& lo, float& hi) {
    asm("mov.b64 {%0, %1}, %2;" : "=f"(lo), "=f"(hi) : "l"(v));
}
__device__ __forceinline__ unsigned long long fma2(unsigned long long a,
                                                   unsigned long long b,
                                                   unsigned long long c) {
    unsigned long long d;
    asm("fma.rn.f32x2 %0, %1, %2, %3;" : "=l"(d) : "l"(a), "l"(b), "l"(c));
    return d;
}

// ---------------- kernel 0: zero accumulators ----------------
__global__ void zero_kernel() {
    int i = blockIdx.x * blockDim.x + threadIdx.x;
    if (i < C_ * A_) g_sums[i] = 0.f;
    if (i < C_) { g_cnti[i] = 0; g_Sc[i] = 0.f; }
    if (i == 0) { g_L1 = 0.f; g_L2 = 0.f; }
}

// ---------------- kernel 1: proto-normalize + exp-sum stats + label counts ----
__global__ void __launch_bounds__(256) protostats_kernel(const float* __restrict__ Proto,
                                                         const float* __restrict__ tarout,
                                                         const int* __restrict__ labels) {
    __shared__ float red[256];
    const int tid = threadIdx.x;

    if (blockIdx.x < 6) {
        const int c = blockIdx.x;
        float4 v = *reinterpret_cast<const float4*>(Proto + c * A_ + (tid << 2));
        float ss = v.x * v.x + v.y * v.y + v.z * v.z + v.w * v.w;
        red[tid] = ss;
        __syncthreads();
        for (int s = 128; s > 0; s >>= 1) {
            if (tid < s) red[tid] += red[tid + s];
            __syncthreads();
        }
        const float inv = 1.0f / fmaxf(sqrtf(red[0]), 1e-12f);
        float4 o = make_float4(v.x * inv, v.y * inv, v.z * inv, v.w * inv);
        *reinterpret_cast<float4*>(g_protoN + c * A_ + (tid << 2)) = o;
    } else if (blockIdx.x < 102) {
        const int sIdx = blockIdx.x - 6;
        const int base = sIdx << 12;
        const int c = (sIdx >> 2) % 6;
        float acc = 0.f;
#pragma unroll
        for (int k = 0; k < 4; k++) {
            float4 t = __ldcs((const float4*)(tarout + base + k * 1024 + (tid << 2)));
            acc += __expf(t.x) + __expf(t.y) + __expf(t.z) + __expf(t.w);
        }
        red[tid] = acc;
        __syncthreads();
        for (int s = 128; s > 0; s >>= 1) {
            if (tid < s) red[tid] += red[tid + s];
            __syncthreads();
        }
        if (tid == 0) atomicAdd(&g_Sc[c], red[0]);
    } else {
        __shared__ int scnt[6];
        if (tid < 6) scnt[tid] = 0;
        __syncthreads();
        const int base = (blockIdx.x - 102) << 12;
        int cnt[6] = {0, 0, 0, 0, 0, 0};
#pragma unroll
        for (int k = 0; k < 16; k++) {
            int l = labels[base + k * 256 + tid];
#pragma unroll
            for (int c = 0; c < 6; c++) cnt[c] += (l == c);
        }
#pragma unroll
        for (int c = 0; c < 6; c++) {
            int w = __reduce_add_sync(0xffffffffu, cnt[c]);
            if ((tid & 31) == 0 && w) atomicAdd(&scnt[c], w);
        }
        __syncthreads();
        if (tid < 6 && scnt[tid]) atomicAdd(&g_cnti[tid], scnt[tid]);
    }
}

// ================= mega kernel: seg + contrast in one launch =================

__device__ __forceinline__ void seg_accum(int c, const float4& v, float4 acc[6]) {
    if ((unsigned)c >= 6u) return;
    switch (c) {
#define SEG_CASE(i) \
        case i: acc[i].x += v.x; acc[i].y += v.y; acc[i].z += v.z; acc[i].w += v.w; break;
        SEG_CASE(0) SEG_CASE(1) SEG_CASE(2) SEG_CASE(3) SEG_CASE(4) SEG_CASE(5)
#undef SEG_CASE
    }
}

__device__ __forceinline__ void seg_body(int segIdx,
                                         const float* __restrict__ src,
                                         const int* __restrict__ labels) {
    const int col = threadIdx.x << 2;
    float4 acc[6];
#pragma unroll
    for (int c = 0; c < 6; c++) acc[c] = make_float4(0.f, 0.f, 0.f, 0.f);

    const int stride = SEG_GRID;
    int r = segIdx;
    for (; r + 3 * stride < NROWS; r += 4 * stride) {
        int l0 = labels[r];
        int l1 = labels[r + stride];
        int l2 = labels[r + 2 * stride];
        int l3 = labels[r + 3 * stride];
        float4 v0 = __ldcs((const float4*)(src + (size_t)r * A_ + col));
        float4 v1 = __ldcs((const float4*)(src + (size_t)(r + stride) * A_ + col));
        float4 v2 = __ldcs((const float4*)(src + (size_t)(r + 2 * stride) * A_ + col));
        float4 v3 = __ldcs((const float4*)(src + (size_t)(r + 3 * stride) * A_ + col));
        seg_accum(l0, v0, acc);
        seg_accum(l1, v1, acc);
        seg_accum(l2, v2, acc);
        seg_accum(l3, v3, acc);
    }
    for (; r < NROWS; r += stride) {
        int l0 = labels[r];
        float4 v0 = __ldcs((const float4*)(src + (size_t)r * A_ + col));
        seg_accum(l0, v0, acc);
    }

#pragma unroll
    for (int c = 0; c < 6; c++) {
        atomicAdd(&g_sums[c * A_ + col + 0], acc[c].x);
        atomicAdd(&g_sums[c * A_ + col + 1], acc[c].y);
        atomicAdd(&g_sums[c * A_ + col + 2], acc[c].z);
        atomicAdd(&g_sums[c * A_ + col + 3], acc[c].w);
    }
}

// contrast tile body. smem passed in from mega kernel.
__device__ __forceinline__ void contrast_body(int T,
                                              const float* __restrict__ tarfeat,
                                              const float* __restrict__ tarout,
                                              float* sProto, float (*sEx)[256], float* sRed) {
    const int tid = threadIdx.x;
    const int lane = tid & 31;
    const int wid = tid >> 5;

    for (int i = tid; i < C_ * A_ / 4; i += 256)
        reinterpret_cast<float4*>(sProto)[i] = reinterpret_cast<const float4*>(g_protoN)[i];
    __syncthreads();

    const int b = T >> 7;                 // 128 tiles per image
    const int pixBase = (T & 127) << 7;   // 128 pixels per tile
    const int pixLoc = tid & 127;
    const int chBase = (tid >> 7) << 9;   // 0 or 512

    const float* p = tarfeat + (size_t)b * ((size_t)A_ * HW_)
                   + (size_t)chBase * HW_ + pixBase + pixLoc;
    const float* pf = sProto + chBase;

    unsigned long long d2[6], ss2 = 0ull;
#pragma unroll
    for (int c = 0; c < 6; c++) d2[c] = 0ull;

#pragma unroll 1
    for (int a = 0; a < 512; a += 16) {
        float v[16];
#pragma unroll
        for (int j = 0; j < 16; j++) v[j] = __ldcs(p + (size_t)j * HW_);
        p += (size_t)16 * HW_;
#pragma unroll
        for (int jq = 0; jq < 4; jq++) {        // 4 channels per step
            unsigned long long vv0 = pk(v[4 * jq + 0], v[4 * jq + 1]);
            unsigned long long vv1 = pk(v[4 * jq + 2], v[4 * jq + 3]);
            ss2 = fma2(vv0, vv0, ss2);
            ss2 = fma2(vv1, vv1, ss2);
#pragma unroll
            for (int c = 0; c < 6; c++) {
                float4 pp = *reinterpret_cast<const float4*>(pf + c * A_ + a + 4 * jq);
                d2[c] = fma2(vv0, pk(pp.x, pp.y), d2[c]);
                d2[c] = fma2(vv1, pk(pp.z, pp.w), d2[c]);
            }
        }
    }

#pragma unroll
    for (int c = 0; c < 6; c++) {
        float lo, hi;
        upk(d2[c], lo, hi);
        sEx[c][tid] = lo + hi;
    }
    {
        float lo, hi;
        upk(ss2, lo, hi);
        sEx[6][tid] = lo + hi;
    }
    __syncthreads();

    float L1p = 0.f, L2p = 0.f;
    if (tid < 128) {
        float d[6], ss;
#pragma unroll
        for (int c = 0; c < 6; c++) d[c] = sEx[c][tid] + sEx[c][tid + 128];
        ss = sEx[6][tid] + sEx[6][tid + 128];

        const float inv = rsqrtf(fmaxf(ss, 1e-24f));
        const int pix = pixBase + tid;
        const float* to = tarout + (size_t)b * ((size_t)C_ * HW_) + pix;

        float e1[6], s1 = 0.f;
#pragma unroll
        for (int c = 0; c < 6; c++) {
            e1[c] = __expf(to[(size_t)c * HW_]);
            s1 += e1[c];
        }
#pragma unroll
        for (int c = 0; c < 6; c++) {
            float con = d[c] * inv;
            L1p = fmaf(e1[c], con, L1p);
            L2p = fmaf(e1[c] * (1.0f / g_Sc[c]), con, L2p);
        }
        L1p /= s1;
    }

#pragma unroll
    for (int o = 16; o > 0; o >>= 1) {
        L1p += __shfl_xor_sync(0xffffffffu, L1p, o);
        L2p += __shfl_xor_sync(0xffffffffu, L2p, o);
    }
    if (lane == 0) { sRed[wid] = L1p; sRed[8 + wid] = L2p; }
    __syncthreads();
    if (tid == 0) {
        float a1 = 0.f, a2 = 0.f;
#pragma unroll
        for (int w = 0; w < 8; w++) { a1 += sRed[w]; a2 += sRed[8 + w]; }
        atomicAdd(&g_L1, a1);
        atomicAdd(&g_L2, a2);
    }
}

// blocks interleaved: even bids < 1024 -> contrast tile bid/2 (0..511)
//                     odd  bids < 1024 -> seg index bid/2   (0..511)
//                     bids >= 1024     -> seg index bid-512 (512..591)
__global__ void __launch_bounds__(256, 4) mega_kernel(const float* __restrict__ srcfeat,
                                                      const int* __restrict__ labels,
                                                      const float* __restrict__ tarfeat,
                                                      const float* __restrict__ tarout) {
    __shared__ float sProto[C_ * A_];   // 24 KB
    __shared__ float sEx[7][256];       // 7 KB
    __shared__ float sRed[16];

    const int bid = blockIdx.x;
    if (bid < 1024) {
        if ((bid & 1) == 0) contrast_body(bid >> 1, tarfeat, tarout, sProto, sEx, sRed);
        else                seg_body(bid >> 1, srcfeat, labels);
    } else {
        seg_body(bid - 512, srcfeat, labels);
    }
}

// ---------------- finalize mean + loss ----------------
__global__ void meanfin_kernel(float* __restrict__ out, int out_size) {
    int i = blockIdx.x * blockDim.x + threadIdx.x;
    if (i < C_ * A_ && (i + 1) < out_size)
        out[1 + i] = g_sums[i] / fmaxf((float)g_cnti[i >> 10], 1.0f);
    if (i == 0 && out_size >= 1) {
        float loss1 = 1.0f - g_L1 * (1.0f / (float)NPIX);
        float loss2 = 1.0f - g_L2 * (1.0f / (float)C_);
        out[0] = loss1 + loss2;
    }
}

// ---------------- launch ----------------
extern "C" void kernel_launch(void* const* d_in, const int* in_sizes, int n_in,
                              void* d_out, int out_size) {
    const float* Proto   = (const float*)d_in[0];
    const float* srcfeat = (const float*)d_in[1];
    const float* tarfeat = (const float*)d_in[2];
    const float* tarout  = (const float*)d_in[3];
    const int* labels    = (const int*)d_in[4];
    float* out = (float*)d_out;

    zero_kernel<<<24, 256>>>();
    protostats_kernel<<<118, 256>>>(Proto, tarout, labels);
    mega_kernel<<<MEGA_GRID, 256>>>(srcfeat, labels, tarfeat, tarout);
    meanfin_kernel<<<24, 256>>>(out, out_size);
}